// round 13
// baseline (speedup 1.0000x reference)
#include <cuda_runtime.h>
#include <cstdint>
#include <math.h>

#define NN     4096
#define HDIM   256
#define HEADS  4
#define HD     64
#define EC     131072
#define TOPK   15
#define CAP    160
#define RT     256      // threads per block
#define CPT    16       // candidates per thread
#define BUFSZ  256
#define GRID   592      // 4 blocks/SM
#define NWARPS (GRID * 8)
#define MWORDS (NN * NN / 32)
#define FULLM  0xffffffffu

// ---------------- device scratch ----------------
__device__ float2 g_vd[HEADS][HDIM];
__device__ float2 g_vs[HEADS][HDIM];
__device__ float4 g_sd[NN];
__device__ float4 g_ss[NN];
__device__ float  g_badj[NN];            // act_j ? 0.15*sum(ss_j) : -inf
__device__ int    g_cur[NN];
__device__ ulonglong2 g_edge[NN * CAP];  // .x = (pos<<32)|float_bits(w), .y = col
__device__ unsigned g_mbits[MWORDS];     // bitpacked sector mask (2 MB, L2-resident)
__device__ unsigned g_tick;
__device__ unsigned g_exit;

// ---------------- dynamic smem ----------------
struct CSmem {
    float    corr[NN];               // 16 KB resolved corr weights
    unsigned kk[NN];                 // 16 KB staged keys
    unsigned long long buf[BUFSZ];   // 2 KB
    unsigned long long sel[TOPK];
    float    ewt[CAP];
    int      ecol[CAP];
    int      epos[CAP];
    int      hist1[1024];            // 4 KB, bins = key >> 22
    int      hist2[256];             // 1 KB, bins = (key >> 14) & 0xFF
    int      cnt, B1, above1, B2, above2, sbyte;
};

// ---------------- double-single helper ----------------
__device__ __forceinline__ void dsadd(float& s, float& c, float p, float pe) {
    float t = s + p;
    float z = t - s;
    float e = (s - (t - z)) + (p - z);
    s = t;
    c += e + pe;
}

// global barrier #gen (1-based)
__device__ __forceinline__ void gbar(int gen) {
    __syncthreads();
    if (threadIdx.x == 0) {
        __threadfence();
        atomicAdd(&g_tick, 1u);
        unsigned target = (unsigned)gen * GRID;
        while (*(volatile unsigned*)&g_tick < target) { }
    }
    __syncthreads();
}

// warp0: largest bin B (of 32*BPL) with suffix-count >= K, via 2-level shfl scan
template <int BPL>
__device__ __forceinline__ void scan_h(const int* __restrict__ hist, int K,
                                       int* outB, int* outAbove) {
    int lane = threadIdx.x & 31;
    int s = 0;
    #pragma unroll
    for (int r = 0; r < BPL; r++) s += hist[lane * BPL + r];
    int run = s;                       // suffix over super-bins incl self
    #pragma unroll
    for (int off = 1; off < 32; off <<= 1) {
        int t = __shfl_down_sync(FULLM, run, off);
        if (lane + off < 32) run += t;
    }
    int above = run - s;
    unsigned bal = __ballot_sync(FULLM, run >= K);
    int SB = (bal == 0) ? 0 : (31 - __clz(bal));
    int aboveSB = (bal == 0) ? 0 : __shfl_sync(FULLM, above, SB);
    // level 2 within super-bin SB
    int hv = (lane < BPL) ? hist[SB * BPL + lane] : 0;
    int run2 = hv;
    #pragma unroll
    for (int off = 1; off < 32; off <<= 1) {
        int t = __shfl_down_sync(FULLM, run2, off);
        if (lane + off < 32) run2 += t;
    }
    int above2 = run2 - hv;
    unsigned bal2 = __ballot_sync(FULLM, aboveSB + run2 >= K);
    int bl = (bal2 == 0) ? 0 : (31 - __clz(bal2));
    int outA = (bal2 == 0) ? 0 : (aboveSB + __shfl_sync(FULLM, above2, bl));
    if (lane == 0) {
        *outB = SB * BPL + bl;
        *outAbove = outA;
    }
}

// ---------------- the one fused kernel ----------------
__global__ __launch_bounds__(RT, 4) void k_all(const float* __restrict__ E,
                                               const float* __restrict__ W,
                                               const float* __restrict__ att,
                                               const float* __restrict__ lambda_p,
                                               const uint8_t* __restrict__ mask,
                                               const uint8_t* __restrict__ act,
                                               const int* __restrict__ eidx,
                                               const float* __restrict__ ew,
                                               float* __restrict__ out) {
    extern __shared__ CSmem smem[];
    CSmem* S = smem;

    const int bid = blockIdx.x;
    const int tid = threadIdx.x;
    const int lane = tid & 31;
    const int wid = tid >> 5;

    // ================= PHASE A =================
    // per-block bool-width detection (redundant, removes ordering dependency)
    if (tid == 0) S->sbyte = 0;
    __syncthreads();
    {
        const unsigned* mw = (const unsigned*)mask;
        #pragma unroll 4
        for (int t = tid; t < 4096; t += RT) {
            unsigned w = mw[t];
            if (w > 1u) {
                unsigned b0 = w & 0xFF, b1 = (w >> 8) & 0xFF,
                         b2 = (w >> 16) & 0xFF, b3 = w >> 24;
                if (b0 <= 1u && b1 <= 1u && b2 <= 1u && b3 <= 1u) S->sbyte = 1;
            }
        }
    }
    __syncthreads();
    const int is_byte = S->sbyte;

    if (bid < 16) {
        g_cur[bid * RT + tid] = 0;
    } else if (bid < 20) {
        int pr = (bid - 16) * RT + tid;   // 0..1023
        int h = pr >> 8;
        int k = pr & 255;
        float sd = 0.f, cd = 0.f, ss = 0.f, cs = 0.f;
        #pragma unroll 8
        for (int dd = 0; dd < HD; dd++) {
            float w   = W[(h * HD + dd) * HDIM + k];
            float ad  = att[h * 2 * HD + dd];
            float as_ = att[h * 2 * HD + HD + dd];
            float p = ad * w;  float pe = fmaf(ad, w, -p);
            dsadd(sd, cd, p, pe);
            p = as_ * w;       pe = fmaf(as_, w, -p);
            dsadd(ss, cs, p, pe);
        }
        float hi = sd + cd;
        g_vd[h][k] = make_float2(hi, (sd - hi) + cd);
        hi = ss + cs;
        g_vs[h][k] = make_float2(hi, (ss - hi) + cs);
    }

    // bitpack mask: all 4736 warps, ballot per 32 elems
    {
        int gw = bid * 8 + wid;
        if (is_byte) {
            #pragma unroll 2
            for (int Wd = gw; Wd < MWORDS; Wd += NWARPS) {
                unsigned bit = __ballot_sync(FULLM, mask[(size_t)Wd * 32 + lane] != 0);
                if (lane == 0) g_mbits[Wd] = bit;
            }
        } else {
            const unsigned* m32 = (const unsigned*)mask;
            #pragma unroll 2
            for (int Wd = gw; Wd < MWORDS; Wd += NWARPS) {
                unsigned bit = __ballot_sync(FULLM, m32[(size_t)Wd * 32 + lane] != 0u);
                if (lane == 0) g_mbits[Wd] = bit;
            }
        }
    }
    gbar(1);

    // ================= PHASE B: sds (0..511) + scatter (512..591) ==========
    if (bid < 512) {
        int g = bid * 8 + wid;
        const float* er = E + (size_t)g * HDIM;
        float s[8], c[8];
        #pragma unroll
        for (int a = 0; a < 8; a++) { s[a] = 0.f; c[a] = 0.f; }
        for (int k = lane; k < HDIM; k += 32) {
            float e = er[k];
            #pragma unroll
            for (int h = 0; h < HEADS; h++) {
                float2 v = g_vd[h][k];
                float p = e * v.x;
                float pe = fmaf(e, v.x, -p);
                pe = fmaf(e, v.y, pe);
                dsadd(s[h], c[h], p, pe);
                v = g_vs[h][k];
                p = e * v.x;
                pe = fmaf(e, v.x, -p);
                pe = fmaf(e, v.y, pe);
                dsadd(s[4 + h], c[4 + h], p, pe);
            }
        }
        #pragma unroll
        for (int off = 16; off; off >>= 1) {
            #pragma unroll
            for (int a = 0; a < 8; a++) {
                float os = __shfl_down_sync(FULLM, s[a], off);
                float oc = __shfl_down_sync(FULLM, c[a], off);
                float t = s[a] + os;
                float z = t - s[a];
                c[a] += oc + ((s[a] - (t - z)) + (os - z));
                s[a] = t;
            }
        }
        if (lane == 0) {
            g_sd[g] = make_float4(s[0] + c[0], s[1] + c[1], s[2] + c[2], s[3] + c[3]);
            float t0 = s[4] + c[4], t1 = s[5] + c[5], t2 = s[6] + c[6], t3 = s[7] + c[7];
            g_ss[g] = make_float4(t0, t1, t2, t3);
            bool aj = is_byte ? (act[g] != 0) : (((const unsigned*)act)[g] != 0u);
            g_badj[g] = aj ? 0.15f * ((t0 + t1) + (t2 + t3)) : -INFINITY;
        }
    } else {
        for (int e = (bid - 512) * RT + tid; e < EC; e += 80 * RT) {
            int r = eidx[e];
            int cc = eidx[EC + e];
            int p = atomicAdd(&g_cur[r], 1);
            if (p < CAP) {
                ulonglong2 rec;
                rec.x = ((unsigned long long)(unsigned)e << 32) |
                        (unsigned long long)__float_as_uint(ew[e]);
                rec.y = (unsigned long long)(unsigned)cc;
                g_edge[r * CAP + p] = rec;
            }
        }
    }
    // zero this block's corr table once (maintained incrementally afterward)
    #pragma unroll
    for (int k = 0; k < NN / RT; k++) S->corr[tid + k * RT] = 0.f;
    gbar(2);

    // ================= PHASE C: rows =================
    const float lam = __ldg(lambda_p);

    for (int i = bid; i < NN; i += GRID) {
        // ---- P1: init + edge load + last-write-wins resolve ----
        #pragma unroll
        for (int r = 0; r < 4; r++) S->hist1[tid + r * RT] = 0;
        S->hist2[tid] = 0;
        if (tid < TOPK) S->sel[tid] = 0ULL;
        if (tid == RT - 1) S->cnt = 0;
        int cnt = g_cur[i];
        if (cnt > CAP) cnt = CAP;
        if (tid < cnt) {
            ulonglong2 rec = __ldg(&g_edge[i * CAP + tid]);
            S->ecol[tid] = (int)rec.y;
            S->epos[tid] = (int)(rec.x >> 32);
            S->ewt[tid]  = __uint_as_float((unsigned)rec.x);
        }
        __syncthreads();
        if (tid < cnt) {
            int c = S->ecol[tid], p = S->epos[tid];
            bool win = true;
            for (int s = 0; s < cnt; s++)
                if (S->ecol[s] == c && S->epos[s] > p) win = false;
            if (win) S->corr[c] = S->ewt[tid];
        }
        __syncthreads();

        const float4 sdi = __ldg(&g_sd[i]);
        const float ci = 0.15f * ((sdi.x + sdi.y) + (sdi.z + sdi.w));
        const bool acti = is_byte ? (act[i] != 0) : (((const unsigned*)act)[i] != 0u);

        // preload this warp's 16 mask words (1 LDG, then shfl per iter)
        unsigned mword = 0;
        if (lane < CPT) mword = __ldg(&g_mbits[i * (NN / 32) + wid + 8 * lane]);

        // ---- P2: 16 keys -> smem + level-1 histogram (1024 bins) ----
        #pragma unroll 8
        for (int k = 0; k < CPT; k++) {
            int j = tid + k * RT;
            float4 ssj = __ldg(&g_ss[j]);
            float x0 = sdi.x + ssj.x;
            float x1 = sdi.y + ssj.y;
            float x2 = sdi.z + ssj.z;
            float x3 = sdi.w + ssj.w;
            float sa = fabsf(x0) + fabsf(x1);
            float sb = fabsf(x2) + fabsf(x3);
            float w = S->corr[j];
            float a = __ldg(&g_badj[j]);
            unsigned mw = __shfl_sync(FULLM, mword, k);
            bool mj = (mw >> lane) & 1u;
            float sc = ci + fmaf(lam, w, a);
            sc = fmaf(0.1f, sa + sb, sc);
            sc = (acti && mj) ? sc : -INFINITY;
            unsigned u = __float_as_uint(sc);
            u ^= ((unsigned)(((int)u) >> 31)) | 0x80000000u;
            S->kk[j] = u;
            unsigned b1 = u >> 22;
            unsigned peers = __match_any_sync(FULLM, b1);
            if ((peers & ((1u << lane) - 1u)) == 0)
                atomicAdd(&S->hist1[b1], (int)__popc(peers));
        }
        __syncthreads();

        // ---- P3: warp0 scan level-1; other warps clear corr entries ----
        if (wid == 0) {
            scan_h<32>(S->hist1, TOPK, &S->B1, &S->above1);
        } else if (tid - 32 < cnt) {
            S->corr[S->ecol[tid - 32]] = 0.f;
        }
        __syncthreads();
        const int B1 = S->B1;
        const int above1 = S->above1;

        // ---- P4: level-2 histogram (bits [21:14]) within bin B1 ----
        #pragma unroll 8
        for (int k = 0; k < CPT; k++) {
            unsigned u = S->kk[tid + k * RT];
            if ((int)(u >> 22) == B1)
                atomicAdd(&S->hist2[(u >> 14) & 0xFF], 1);
        }
        __syncthreads();

        // ---- P5: level-2 scan ----
        if (wid == 0) scan_h<8>(S->hist2, TOPK - above1, &S->B2, &S->above2);
        __syncthreads();
        const int B2 = S->B2;

        // ---- P6: append candidates ----
        #pragma unroll 8
        for (int k = 0; k < CPT; k++) {
            int j = tid + k * RT;
            unsigned u = S->kk[j];
            int b1k = (int)(u >> 22);
            bool cand = (b1k > B1) || (b1k == B1 && (int)((u >> 14) & 0xFF) >= B2);
            if (cand) {
                int p = atomicAdd(&S->cnt, 1);
                if (p < BUFSZ) {
                    S->buf[p] = ((unsigned long long)u << 32) |
                                (unsigned long long)(0xFFFFFFFFu - (unsigned)j);
                }
            }
        }
        __syncthreads();

        // ---- P7: rank-select top-15 ----
        int n = S->cnt < BUFSZ ? S->cnt : BUFSZ;
        {
            unsigned long long K = (tid < n) ? S->buf[tid] : 0ULL;
            int rank = 0;
            for (int s = 0; s < n; s++) rank += (S->buf[s] > K);
            if (tid < n && rank < TOPK) S->sel[rank] = K;
        }
        __syncthreads();

        // ---- P8: warp0 decode + softmax + write ----
        if (wid == 0) {
            unsigned long long k64 = (lane < TOPK) ? S->sel[lane] : 0ULL;
            unsigned u = (unsigned)(k64 >> 32);
            float v = (u & 0x80000000u) ? __uint_as_float(u ^ 0x80000000u)
                                        : __uint_as_float(~u);
            unsigned j = 0xFFFFFFFFu - (unsigned)(k64 & 0xFFFFFFFFu);
            float v0 = __shfl_sync(FULLM, v, 0);
            float e = (lane < TOPK) ? expf(v - v0) : 0.f;
            float s = e;
            #pragma unroll
            for (int off = 16; off; off >>= 1) s += __shfl_xor_sync(FULLM, s, off);
            if (lane < TOPK) {
                out[(size_t)i * TOPK + lane] = (float)j;
                out[(size_t)NN * TOPK + (size_t)i * TOPK + lane] = (float)i;
                out[2 * (size_t)NN * TOPK + (size_t)i * TOPK + lane] = e / s;
            }
        }
        __syncthreads();
    }

    // ================= epilogue: reset barrier counters =================
    if (tid == 0) {
        __threadfence();
        unsigned t = atomicAdd(&g_exit, 1u);
        if (t == GRID - 1) {
            g_tick = 0;
            g_exit = 0;
            __threadfence();
        }
    }
}

// ---------------- launcher ----------------
extern "C" void kernel_launch(void* const* d_in, const int* in_sizes, int n_in,
                              void* d_out, int out_size) {
    const float*   emb  = (const float*)d_in[0];
    const float*   W    = (const float*)d_in[1];
    const float*   att  = (const float*)d_in[2];
    const float*   lam  = (const float*)d_in[3];
    const uint8_t* mask = (const uint8_t*)d_in[4];
    const uint8_t* act  = (const uint8_t*)d_in[5];
    const int*     eidx = (const int*)d_in[6];
    const float*   ew   = (const float*)d_in[7];
    float* out = (float*)d_out;

    cudaFuncSetAttribute(k_all, cudaFuncAttributeMaxDynamicSharedMemorySize,
                         (int)sizeof(CSmem));
    k_all<<<GRID, RT, sizeof(CSmem)>>>(emb, W, att, lam, mask, act, eidx, ew, out);
}

// round 14
// speedup vs baseline: 1.1909x; 1.1909x over previous
#include <cuda_runtime.h>
#include <cstdint>
#include <math.h>

#define NN     4096
#define HDIM   256
#define HEADS  4
#define HD     64
#define EC     131072
#define TOPK   15
#define CAP    160
#define RT     256      // threads per block
#define CPT    16       // candidates per thread
#define BUFSZ  256
#define GRID   592      // 4 blocks/SM
#define FULLM  0xffffffffu

// ---------------- device scratch ----------------
__device__ float2 g_vd[HEADS][HDIM];
__device__ float2 g_vs[HEADS][HDIM];
__device__ float4 g_sd[NN];
__device__ float4 g_ss[NN];
__device__ float  g_badj[NN];            // act_j ? 0.15*sum(ss_j) : -inf
__device__ int    g_cur[NN];
__device__ ulonglong2 g_edge[NN * CAP];  // .x = (pos<<32)|float_bits(w), .y = col
__device__ int    g_is_byte;
__device__ unsigned g_tick;
__device__ unsigned g_exit;

// ---------------- dynamic smem ----------------
struct CSmem {
    unsigned long long corr[NN];     // 32 KB
    unsigned           kk[NN];       // 16 KB staged keys
    unsigned long long buf[BUFSZ];   // 2 KB
    unsigned long long sel[TOPK];
    int  hist1[1024];                // 4 KB, bins = key >> 22
    int  hist2[256];                 // 1 KB, bins = (key >> 14) & 0xFF
    int  cnt, B1, above1, B2, above2, sbyte;
};

// ---------------- double-single helper ----------------
__device__ __forceinline__ void dsadd(float& s, float& c, float p, float pe) {
    float t = s + p;
    float z = t - s;
    float e = (s - (t - z)) + (p - z);
    s = t;
    c += e + pe;
}

// global barrier #gen (1-based)
__device__ __forceinline__ void gbar(int gen) {
    __syncthreads();
    if (threadIdx.x == 0) {
        __threadfence();
        atomicAdd(&g_tick, 1u);
        unsigned target = (unsigned)gen * GRID;
        while (*(volatile unsigned*)&g_tick < target) { }
    }
    __syncthreads();
}

// warp0: largest bin B (of 32*BPL bins) with suffix-count >= K, 2-level shfl scan
template <int BPL>
__device__ __forceinline__ void scan_h(const int* __restrict__ hist, int K,
                                       int* outB, int* outAbove) {
    int lane = threadIdx.x & 31;
    int s = 0;
    #pragma unroll
    for (int r = 0; r < BPL; r++) s += hist[lane * BPL + r];
    int run = s;                       // suffix-sum over super-bins incl self
    #pragma unroll
    for (int off = 1; off < 32; off <<= 1) {
        int t = __shfl_down_sync(FULLM, run, off);
        if (lane + off < 32) run += t;
    }
    int above = run - s;
    unsigned bal = __ballot_sync(FULLM, run >= K);
    int SB = (bal == 0) ? 0 : (31 - __clz(bal));
    int aboveSB = (bal == 0) ? 0 : __shfl_sync(FULLM, above, SB);
    // level 2 within super-bin SB
    int hv = (lane < BPL) ? hist[SB * BPL + lane] : 0;
    int run2 = hv;
    #pragma unroll
    for (int off = 1; off < 32; off <<= 1) {
        int t = __shfl_down_sync(FULLM, run2, off);
        if (lane + off < 32) run2 += t;
    }
    int above2 = run2 - hv;
    unsigned bal2 = __ballot_sync(FULLM, aboveSB + run2 >= K);
    int bl = (bal2 == 0) ? 0 : (31 - __clz(bal2));
    int outA = (bal2 == 0) ? 0 : (aboveSB + __shfl_sync(FULLM, above2, bl));
    if (lane == 0) {
        *outB = SB * BPL + bl;
        *outAbove = outA;
    }
}

// ---------------- the one fused kernel ----------------
__global__ __launch_bounds__(RT, 4) void k_all(const float* __restrict__ E,
                                               const float* __restrict__ W,
                                               const float* __restrict__ att,
                                               const float* __restrict__ lambda_p,
                                               const uint8_t* __restrict__ mask,
                                               const uint8_t* __restrict__ act,
                                               const int* __restrict__ eidx,
                                               const float* __restrict__ ew,
                                               float* __restrict__ out) {
    extern __shared__ CSmem smem[];
    CSmem* S = smem;

    const int bid = blockIdx.x;
    const int tid = threadIdx.x;
    const int lane = tid & 31;
    const int wid = tid >> 5;

    // ================= PHASE A =================
    if (bid < 16) {
        g_cur[bid * RT + tid] = 0;
    } else if (bid < 20) {
        int pr = (bid - 16) * RT + tid;   // 0..1023
        int h = pr >> 8;
        int k = pr & 255;
        float sd = 0.f, cd = 0.f, ss = 0.f, cs = 0.f;
        #pragma unroll 8
        for (int dd = 0; dd < HD; dd++) {
            float w   = W[(h * HD + dd) * HDIM + k];
            float ad  = att[h * 2 * HD + dd];
            float as_ = att[h * 2 * HD + HD + dd];
            float p = ad * w;  float pe = fmaf(ad, w, -p);
            dsadd(sd, cd, p, pe);
            p = as_ * w;       pe = fmaf(as_, w, -p);
            dsadd(ss, cs, p, pe);
        }
        float hi = sd + cd;
        g_vd[h][k] = make_float2(hi, (sd - hi) + cd);
        hi = ss + cs;
        g_vs[h][k] = make_float2(hi, (ss - hi) + cs);
    } else if (bid == 20) {
        if (tid == 0) S->sbyte = 0;
        __syncthreads();
        const unsigned* mw = (const unsigned*)mask;
        for (int t = tid; t < 4096; t += RT) {
            unsigned w = mw[t];
            if (w > 1u) {
                unsigned b0 = w & 0xFF, b1 = (w >> 8) & 0xFF,
                         b2 = (w >> 16) & 0xFF, b3 = w >> 24;
                if (b0 <= 1u && b1 <= 1u && b2 <= 1u && b3 <= 1u) S->sbyte = 1;
            }
        }
        __syncthreads();
        if (tid == 0) g_is_byte = S->sbyte;
    }
    gbar(1);

    // ================= PHASE B: sds (0..511) + scatter (512..591) ==========
    if (bid < 512) {
        int g = bid * 8 + wid;
        const float* er = E + (size_t)g * HDIM;
        float s[8], c[8];
        #pragma unroll
        for (int a = 0; a < 8; a++) { s[a] = 0.f; c[a] = 0.f; }
        for (int k = lane; k < HDIM; k += 32) {
            float e = er[k];
            #pragma unroll
            for (int h = 0; h < HEADS; h++) {
                float2 v = g_vd[h][k];
                float p = e * v.x;
                float pe = fmaf(e, v.x, -p);
                pe = fmaf(e, v.y, pe);
                dsadd(s[h], c[h], p, pe);
                v = g_vs[h][k];
                p = e * v.x;
                pe = fmaf(e, v.x, -p);
                pe = fmaf(e, v.y, pe);
                dsadd(s[4 + h], c[4 + h], p, pe);
            }
        }
        #pragma unroll
        for (int off = 16; off; off >>= 1) {
            #pragma unroll
            for (int a = 0; a < 8; a++) {
                float os = __shfl_down_sync(FULLM, s[a], off);
                float oc = __shfl_down_sync(FULLM, c[a], off);
                float t = s[a] + os;
                float z = t - s[a];
                c[a] += oc + ((s[a] - (t - z)) + (os - z));
                s[a] = t;
            }
        }
        if (lane == 0) {
            g_sd[g] = make_float4(s[0] + c[0], s[1] + c[1], s[2] + c[2], s[3] + c[3]);
            float t0 = s[4] + c[4], t1 = s[5] + c[5], t2 = s[6] + c[6], t3 = s[7] + c[7];
            g_ss[g] = make_float4(t0, t1, t2, t3);
            bool aj = g_is_byte ? (act[g] != 0) : (((const unsigned*)act)[g] != 0u);
            g_badj[g] = aj ? 0.15f * ((t0 + t1) + (t2 + t3)) : -INFINITY;
        }
    } else {
        for (int e = (bid - 512) * RT + tid; e < EC; e += 80 * RT) {
            int r = eidx[e];
            int cc = eidx[EC + e];
            int p = atomicAdd(&g_cur[r], 1);
            if (p < CAP) {
                ulonglong2 rec;
                rec.x = ((unsigned long long)(unsigned)e << 32) |
                        (unsigned long long)__float_as_uint(ew[e]);
                rec.y = (unsigned long long)(unsigned)cc;
                g_edge[r * CAP + p] = rec;
            }
        }
    }
    // zero this block's corr table once (maintained incrementally afterward)
    #pragma unroll
    for (int k = 0; k < NN / RT; k++) S->corr[tid + k * RT] = 0ULL;
    gbar(2);

    // ================= PHASE C: rows =================
    const float lam = __ldg(lambda_p);
    const int is_byte = g_is_byte;

    for (int i = bid; i < NN; i += GRID) {
        // ---- P1: row init + edge scatter (corr already zeroed) ----
        #pragma unroll
        for (int r = 0; r < 4; r++) S->hist1[tid + r * RT] = 0;
        S->hist2[tid] = 0;
        if (tid < TOPK) S->sel[tid] = 0ULL;
        if (tid == RT - 1) S->cnt = 0;
        int cnt = g_cur[i];
        if (cnt > CAP) cnt = CAP;
        if (tid < cnt) {
            ulonglong2 rec = __ldg(&g_edge[i * CAP + tid]);
            atomicMax(&S->corr[(int)rec.y], rec.x);
        }
        __syncthreads();

        const float4 sdi = __ldg(&g_sd[i]);
        const float ci = 0.15f * ((sdi.x + sdi.y) + (sdi.z + sdi.w));
        const uint8_t*  mrow8  = mask + (size_t)i * NN;
        const unsigned* mrow32 = (const unsigned*)mask + (size_t)i * NN;
        const bool acti = is_byte ? (act[i] != 0) : (((const unsigned*)act)[i] != 0u);

        // ---- P2: compute 16 keys -> smem + level-1 histogram (1024 bins) ----
        #pragma unroll 8
        for (int k = 0; k < CPT; k++) {
            int j = tid + k * RT;
            float4 ssj = __ldg(&g_ss[j]);
            float x0 = sdi.x + ssj.x;
            float x1 = sdi.y + ssj.y;
            float x2 = sdi.z + ssj.z;
            float x3 = sdi.w + ssj.w;
            float sa = fabsf(x0) + fabsf(x1);
            float sb = fabsf(x2) + fabsf(x3);
            float w = __uint_as_float((unsigned)(((const unsigned*)S->corr)[2 * j]));
            float a = __ldg(&g_badj[j]);
            bool mj = is_byte ? (mrow8[j] != 0) : (mrow32[j] != 0u);
            float sc = ci + fmaf(lam, w, a);
            sc = fmaf(0.1f, sa + sb, sc);
            sc = (acti && mj) ? sc : -INFINITY;
            unsigned u = __float_as_uint(sc);
            u ^= ((unsigned)(((int)u) >> 31)) | 0x80000000u;
            S->kk[j] = u;
            unsigned b1 = u >> 22;
            unsigned peers = __match_any_sync(FULLM, b1);
            if ((peers & ((1u << lane) - 1u)) == 0)
                atomicAdd(&S->hist1[b1], (int)__popc(peers));
        }
        __syncthreads();

        // ---- P3: warp0 scans level-1; warps 1..7 re-zero corr for next row --
        if (wid == 0) {
            scan_h<32>(S->hist1, TOPK, &S->B1, &S->above1);
        } else {
            for (int j = tid - 32; j < NN; j += RT - 32) S->corr[j] = 0ULL;
        }
        __syncthreads();
        const int B1 = S->B1;
        const int above1 = S->above1;

        // ---- P4: level-2 histogram (bits [21:14]) within bin B1 ----
        #pragma unroll 8
        for (int k = 0; k < CPT; k++) {
            unsigned u = S->kk[tid + k * RT];
            if ((int)(u >> 22) == B1)
                atomicAdd(&S->hist2[(u >> 14) & 0xFF], 1);
        }
        __syncthreads();

        // ---- P5: level-2 scan ----
        if (wid == 0) scan_h<8>(S->hist2, TOPK - above1, &S->B2, &S->above2);
        __syncthreads();
        const int B2 = S->B2;

        // ---- P6: append candidates ----
        #pragma unroll 8
        for (int k = 0; k < CPT; k++) {
            int j = tid + k * RT;
            unsigned u = S->kk[j];
            int b1k = (int)(u >> 22);
            bool cand = (b1k > B1) || (b1k == B1 && (int)((u >> 14) & 0xFF) >= B2);
            if (cand) {
                int p = atomicAdd(&S->cnt, 1);
                if (p < BUFSZ) {
                    S->buf[p] = ((unsigned long long)u << 32) |
                                (unsigned long long)(0xFFFFFFFFu - (unsigned)j);
                }
            }
        }
        __syncthreads();

        // ---- P7: rank-select top-15 ----
        int n = S->cnt < BUFSZ ? S->cnt : BUFSZ;
        {
            unsigned long long K = (tid < n) ? S->buf[tid] : 0ULL;
            int rank = 0;
            for (int s = 0; s < n; s++) rank += (S->buf[s] > K);
            if (tid < n && rank < TOPK) S->sel[rank] = K;
        }
        __syncthreads();

        // ---- P8: warp0 decode + softmax + write ----
        if (wid == 0) {
            unsigned long long k64 = (lane < TOPK) ? S->sel[lane] : 0ULL;
            unsigned u = (unsigned)(k64 >> 32);
            float v = (u & 0x80000000u) ? __uint_as_float(u ^ 0x80000000u)
                                        : __uint_as_float(~u);
            unsigned j = 0xFFFFFFFFu - (unsigned)(k64 & 0xFFFFFFFFu);
            float v0 = __shfl_sync(FULLM, v, 0);
            float e = (lane < TOPK) ? expf(v - v0) : 0.f;
            float s = e;
            #pragma unroll
            for (int off = 16; off; off >>= 1) s += __shfl_xor_sync(FULLM, s, off);
            if (lane < TOPK) {
                out[(size_t)i * TOPK + lane] = (float)j;
                out[(size_t)NN * TOPK + (size_t)i * TOPK + lane] = (float)i;
                out[2 * (size_t)NN * TOPK + (size_t)i * TOPK + lane] = e / s;
            }
        }
        __syncthreads();
    }

    // ================= epilogue: reset barrier counters =================
    if (tid == 0) {
        __threadfence();
        unsigned t = atomicAdd(&g_exit, 1u);
        if (t == GRID - 1) {
            g_tick = 0;
            g_exit = 0;
            __threadfence();
        }
    }
}

// ---------------- launcher ----------------
extern "C" void kernel_launch(void* const* d_in, const int* in_sizes, int n_in,
                              void* d_out, int out_size) {
    const float*   emb  = (const float*)d_in[0];
    const float*   W    = (const float*)d_in[1];
    const float*   att  = (const float*)d_in[2];
    const float*   lam  = (const float*)d_in[3];
    const uint8_t* mask = (const uint8_t*)d_in[4];
    const uint8_t* act  = (const uint8_t*)d_in[5];
    const int*     eidx = (const int*)d_in[6];
    const float*   ew   = (const float*)d_in[7];
    float* out = (float*)d_out;

    cudaFuncSetAttribute(k_all, cudaFuncAttributeMaxDynamicSharedMemorySize,
                         (int)sizeof(CSmem));
    k_all<<<GRID, RT, sizeof(CSmem)>>>(emb, W, att, lam, mask, act, eidx, ew, out);
}

// round 15
// speedup vs baseline: 1.3529x; 1.1360x over previous
#include <cuda_runtime.h>
#include <cstdint>
#include <math.h>

#define NN     4096
#define HDIM   256
#define HEADS  4
#define HD     64
#define EC     131072
#define TOPK   15
#define CAP    160
#define RT     256      // threads per block
#define CPT    16       // candidates per thread
#define BUFSZ  256
#define GRID   740      // 5 blocks/SM on 148 SMs -> all co-resident
#define FULLM  0xffffffffu

// ---------------- device scratch ----------------
__device__ float2 g_vd[HEADS][HDIM];
__device__ float2 g_vs[HEADS][HDIM];
__device__ float4 g_sd[NN];
__device__ float4 g_ss[NN];
__device__ float  g_badj[NN];            // act_j ? 0.15*sum(ss_j) : -inf
__device__ int    g_cur[NN];
__device__ ulonglong2 g_edge[NN * CAP];  // .x = (pos<<32)|float_bits(w), .y = col
__device__ int    g_is_byte;
__device__ unsigned g_tick;
__device__ unsigned g_exit;

// ---------------- dynamic smem (~39 KB) ----------------
struct CSmem {
    float    corr[NN];               // 16 KB resolved corr weights (0 = none)
    unsigned kk[NN];                 // 16 KB staged keys
    unsigned long long buf[BUFSZ];   // 2 KB
    unsigned long long sel[TOPK];
    float    ewt[CAP];
    int      ecol[CAP];
    int      epos[CAP];
    int      hist1[256];             // 1 KB, bins = key >> 24
    int      hist2[256];             // 1 KB, bins = (key >> 16) & 0xFF
    int      cnt, B1, above1, B2, above2, sbyte;
};

// ---------------- double-single helper ----------------
__device__ __forceinline__ void dsadd(float& s, float& c, float p, float pe) {
    float t = s + p;
    float z = t - s;
    float e = (s - (t - z)) + (p - z);
    s = t;
    c += e + pe;
}

// global barrier #gen (1-based)
__device__ __forceinline__ void gbar(int gen) {
    __syncthreads();
    if (threadIdx.x == 0) {
        __threadfence();
        atomicAdd(&g_tick, 1u);
        unsigned target = (unsigned)gen * GRID;
        while (*(volatile unsigned*)&g_tick < target) { }
    }
    __syncthreads();
}

// warp0: largest bin B (256 bins) with suffix-count >= K  (R7-proven)
__device__ __forceinline__ void scan_hist(const int* __restrict__ hist, int K,
                                          int* outB, int* outAbove) {
    int lane = threadIdx.x & 31;
    int base = lane * 8;
    int h[8];
    #pragma unroll
    for (int r = 0; r < 8; r++) h[r] = hist[base + r];
    int ls[8];
    int s = 0;
    #pragma unroll
    for (int r = 7; r >= 0; r--) { s += h[r]; ls[r] = s; }
    int run = s;
    #pragma unroll
    for (int off = 1; off < 32; off <<= 1) {
        int t = __shfl_down_sync(FULLM, run, off);
        if (lane + off < 32) run += t;
    }
    int above = run - s;
    int cand = -1, candAbove = 0;
    #pragma unroll
    for (int r = 7; r >= 0; r--) {
        if (cand < 0 && above + ls[r] >= K) {
            cand = base + r;
            candAbove = above + ls[r] - h[r];
        }
    }
    int bestB = cand, bestA = candAbove;
    #pragma unroll
    for (int off = 16; off; off >>= 1) {
        int ob = __shfl_xor_sync(FULLM, bestB, off);
        int oa = __shfl_xor_sync(FULLM, bestA, off);
        if (ob > bestB) { bestB = ob; bestA = oa; }
    }
    if (lane == 0) {
        *outB = (bestB < 0) ? 0 : bestB;
        *outAbove = (bestB < 0) ? 0 : bestA;
    }
}

// ---------------- the one fused kernel ----------------
__global__ __launch_bounds__(RT, 5) void k_all(const float* __restrict__ E,
                                               const float* __restrict__ W,
                                               const float* __restrict__ att,
                                               const float* __restrict__ lambda_p,
                                               const uint8_t* __restrict__ mask,
                                               const uint8_t* __restrict__ act,
                                               const int* __restrict__ eidx,
                                               const float* __restrict__ ew,
                                               float* __restrict__ out) {
    extern __shared__ CSmem smem[];
    CSmem* S = smem;

    const int bid = blockIdx.x;
    const int tid = threadIdx.x;
    const int lane = tid & 31;
    const int wid = tid >> 5;

    // ================= PHASE A =================
    if (bid < 16) {
        g_cur[bid * RT + tid] = 0;
    } else if (bid < 20) {
        int pr = (bid - 16) * RT + tid;   // 0..1023
        int h = pr >> 8;
        int k = pr & 255;
        float sd = 0.f, cd = 0.f, ss = 0.f, cs = 0.f;
        #pragma unroll 8
        for (int dd = 0; dd < HD; dd++) {
            float w   = W[(h * HD + dd) * HDIM + k];
            float ad  = att[h * 2 * HD + dd];
            float as_ = att[h * 2 * HD + HD + dd];
            float p = ad * w;  float pe = fmaf(ad, w, -p);
            dsadd(sd, cd, p, pe);
            p = as_ * w;       pe = fmaf(as_, w, -p);
            dsadd(ss, cs, p, pe);
        }
        float hi = sd + cd;
        g_vd[h][k] = make_float2(hi, (sd - hi) + cd);
        hi = ss + cs;
        g_vs[h][k] = make_float2(hi, (ss - hi) + cs);
    } else if (bid == 20) {
        if (tid == 0) S->sbyte = 0;
        __syncthreads();
        const unsigned* mw = (const unsigned*)mask;
        for (int t = tid; t < 4096; t += RT) {
            unsigned w = mw[t];
            if (w > 1u) {
                unsigned b0 = w & 0xFF, b1 = (w >> 8) & 0xFF,
                         b2 = (w >> 16) & 0xFF, b3 = w >> 24;
                if (b0 <= 1u && b1 <= 1u && b2 <= 1u && b3 <= 1u) S->sbyte = 1;
            }
        }
        __syncthreads();
        if (tid == 0) g_is_byte = S->sbyte;
    }
    gbar(1);

    // ================= PHASE B: sds (0..511) + scatter (512..739) ==========
    if (bid < 512) {
        int g = bid * 8 + wid;
        const float* er = E + (size_t)g * HDIM;
        float s[8], c[8];
        #pragma unroll
        for (int a = 0; a < 8; a++) { s[a] = 0.f; c[a] = 0.f; }
        for (int k = lane; k < HDIM; k += 32) {
            float e = er[k];
            #pragma unroll
            for (int h = 0; h < HEADS; h++) {
                float2 v = g_vd[h][k];
                float p = e * v.x;
                float pe = fmaf(e, v.x, -p);
                pe = fmaf(e, v.y, pe);
                dsadd(s[h], c[h], p, pe);
                v = g_vs[h][k];
                p = e * v.x;
                pe = fmaf(e, v.x, -p);
                pe = fmaf(e, v.y, pe);
                dsadd(s[4 + h], c[4 + h], p, pe);
            }
        }
        #pragma unroll
        for (int off = 16; off; off >>= 1) {
            #pragma unroll
            for (int a = 0; a < 8; a++) {
                float os = __shfl_down_sync(FULLM, s[a], off);
                float oc = __shfl_down_sync(FULLM, c[a], off);
                float t = s[a] + os;
                float z = t - s[a];
                c[a] += oc + ((s[a] - (t - z)) + (os - z));
                s[a] = t;
            }
        }
        if (lane == 0) {
            g_sd[g] = make_float4(s[0] + c[0], s[1] + c[1], s[2] + c[2], s[3] + c[3]);
            float t0 = s[4] + c[4], t1 = s[5] + c[5], t2 = s[6] + c[6], t3 = s[7] + c[7];
            g_ss[g] = make_float4(t0, t1, t2, t3);
            bool aj = g_is_byte ? (act[g] != 0) : (((const unsigned*)act)[g] != 0u);
            g_badj[g] = aj ? 0.15f * ((t0 + t1) + (t2 + t3)) : -INFINITY;
        }
    } else {
        for (int e = (bid - 512) * RT + tid; e < EC; e += 228 * RT) {
            int r = eidx[e];
            int cc = eidx[EC + e];
            int p = atomicAdd(&g_cur[r], 1);
            if (p < CAP) {
                ulonglong2 rec;
                rec.x = ((unsigned long long)(unsigned)e << 32) |
                        (unsigned long long)__float_as_uint(ew[e]);
                rec.y = (unsigned long long)(unsigned)cc;
                g_edge[r * CAP + p] = rec;
            }
        }
    }
    // zero this block's corr table once (maintained incrementally afterward)
    #pragma unroll
    for (int k = 0; k < NN / RT; k++) S->corr[tid + k * RT] = 0.f;
    gbar(2);

    // ================= PHASE C: rows =================
    const float lam = __ldg(lambda_p);
    const int is_byte = g_is_byte;

    for (int i = bid; i < NN; i += GRID) {
        // ---- P1: init + edge load + last-write-wins resolve ----
        S->hist1[tid] = 0;
        S->hist2[tid] = 0;
        if (tid < TOPK) S->sel[tid] = 0ULL;
        if (tid == RT - 1) S->cnt = 0;
        int cnt = g_cur[i];
        if (cnt > CAP) cnt = CAP;
        if (tid < cnt) {
            ulonglong2 rec = __ldg(&g_edge[i * CAP + tid]);
            S->ecol[tid] = (int)rec.y;
            S->epos[tid] = (int)(rec.x >> 32);
            S->ewt[tid]  = __uint_as_float((unsigned)rec.x);
        }
        __syncthreads();
        if (tid < cnt) {
            int c = S->ecol[tid], p = S->epos[tid];
            bool win = true;
            for (int s = 0; s < cnt; s++)
                if (S->ecol[s] == c && S->epos[s] > p) win = false;
            if (win) S->corr[c] = S->ewt[tid];
        }
        __syncthreads();

        const float4 sdi = __ldg(&g_sd[i]);
        const float ci = 0.15f * ((sdi.x + sdi.y) + (sdi.z + sdi.w));
        const uint8_t*  mrow8  = mask + (size_t)i * NN;
        const unsigned* mrow32 = (const unsigned*)mask + (size_t)i * NN;
        const bool acti = is_byte ? (act[i] != 0) : (((const unsigned*)act)[i] != 0u);

        // ---- P2: compute 16 keys -> smem + level-1 histogram ----
        #pragma unroll 8
        for (int k = 0; k < CPT; k++) {
            int j = tid + k * RT;
            float4 ssj = __ldg(&g_ss[j]);
            float x0 = sdi.x + ssj.x;
            float x1 = sdi.y + ssj.y;
            float x2 = sdi.z + ssj.z;
            float x3 = sdi.w + ssj.w;
            float sa = fabsf(x0) + fabsf(x1);
            float sb = fabsf(x2) + fabsf(x3);
            float w = S->corr[j];
            float a = __ldg(&g_badj[j]);
            bool mj = is_byte ? (mrow8[j] != 0) : (mrow32[j] != 0u);
            float sc = ci + fmaf(lam, w, a);
            sc = fmaf(0.1f, sa + sb, sc);
            sc = (acti && mj) ? sc : -INFINITY;
            unsigned u = __float_as_uint(sc);
            u ^= ((unsigned)(((int)u) >> 31)) | 0x80000000u;
            S->kk[j] = u;
            unsigned b1 = u >> 24;
            unsigned peers = __match_any_sync(FULLM, b1);
            if ((peers & ((1u << lane) - 1u)) == 0)
                atomicAdd(&S->hist1[b1], (int)__popc(peers));
        }
        __syncthreads();

        // ---- P3: warp0 scans level-1; other threads clear touched corr ----
        if (wid == 0) {
            scan_hist(S->hist1, TOPK, &S->B1, &S->above1);
        } else if (tid - 32 < cnt) {
            S->corr[S->ecol[tid - 32]] = 0.f;
        }
        __syncthreads();
        const int B1 = S->B1;
        const int above1 = S->above1;

        // ---- P4: level-2 histogram within bin B1 ----
        #pragma unroll 8
        for (int k = 0; k < CPT; k++) {
            unsigned u = S->kk[tid + k * RT];
            if ((int)(u >> 24) == B1)
                atomicAdd(&S->hist2[(u >> 16) & 0xFF], 1);
        }
        __syncthreads();

        // ---- P5: level-2 scan ----
        if (wid == 0) scan_hist(S->hist2, TOPK - above1, &S->B2, &S->above2);
        __syncthreads();
        const int B2 = S->B2;

        // ---- P6: append candidates ----
        #pragma unroll 8
        for (int k = 0; k < CPT; k++) {
            int j = tid + k * RT;
            unsigned u = S->kk[j];
            int b1k = (int)(u >> 24);
            bool cand = (b1k > B1) || (b1k == B1 && (int)((u >> 16) & 0xFF) >= B2);
            if (cand) {
                int p = atomicAdd(&S->cnt, 1);
                if (p < BUFSZ) {
                    S->buf[p] = ((unsigned long long)u << 32) |
                                (unsigned long long)(0xFFFFFFFFu - (unsigned)j);
                }
            }
        }
        __syncthreads();

        // ---- P7: rank-select top-15 ----
        int n = S->cnt < BUFSZ ? S->cnt : BUFSZ;
        {
            unsigned long long K = (tid < n) ? S->buf[tid] : 0ULL;
            int rank = 0;
            for (int s = 0; s < n; s++) rank += (S->buf[s] > K);
            if (tid < n && rank < TOPK) S->sel[rank] = K;
        }
        __syncthreads();

        // ---- P8: warp0 decode + softmax + write ----
        if (wid == 0) {
            unsigned long long k64 = (lane < TOPK) ? S->sel[lane] : 0ULL;
            unsigned u = (unsigned)(k64 >> 32);
            float v = (u & 0x80000000u) ? __uint_as_float(u ^ 0x80000000u)
                                        : __uint_as_float(~u);
            unsigned j = 0xFFFFFFFFu - (unsigned)(k64 & 0xFFFFFFFFu);
            float v0 = __shfl_sync(FULLM, v, 0);
            float e = (lane < TOPK) ? expf(v - v0) : 0.f;
            float s = e;
            #pragma unroll
            for (int off = 16; off; off >>= 1) s += __shfl_xor_sync(FULLM, s, off);
            if (lane < TOPK) {
                out[(size_t)i * TOPK + lane] = (float)j;
                out[(size_t)NN * TOPK + (size_t)i * TOPK + lane] = (float)i;
                out[2 * (size_t)NN * TOPK + (size_t)i * TOPK + lane] = e / s;
            }
        }
        __syncthreads();
    }

    // ================= epilogue: reset barrier counters =================
    if (tid == 0) {
        __threadfence();
        unsigned t = atomicAdd(&g_exit, 1u);
        if (t == GRID - 1) {
            g_tick = 0;
            g_exit = 0;
            __threadfence();
        }
    }
}

// ---------------- launcher ----------------
extern "C" void kernel_launch(void* const* d_in, const int* in_sizes, int n_in,
                              void* d_out, int out_size) {
    const float*   emb  = (const float*)d_in[0];
    const float*   W    = (const float*)d_in[1];
    const float*   att  = (const float*)d_in[2];
    const float*   lam  = (const float*)d_in[3];
    const uint8_t* mask = (const uint8_t*)d_in[4];
    const uint8_t* act  = (const uint8_t*)d_in[5];
    const int*     eidx = (const int*)d_in[6];
    const float*   ew   = (const float*)d_in[7];
    float* out = (float*)d_out;

    cudaFuncSetAttribute(k_all, cudaFuncAttributeMaxDynamicSharedMemorySize,
                         (int)sizeof(CSmem));
    k_all<<<GRID, RT, sizeof(CSmem)>>>(emb, W, att, lam, mask, act, eidx, ew, out);
}

// round 16
// speedup vs baseline: 1.4458x; 1.0687x over previous
#include <cuda_runtime.h>
#include <cstdint>
#include <math.h>

#define NN     4096
#define HDIM   256
#define HEADS  4
#define HD     64
#define EC     131072
#define TOPK   15
#define CAP    160      // g_edge bucket capacity (global)
#define ECAP   96       // per-row edge list loaded to smem (Poisson(32); +11 sigma)
#define RT     256      // threads per block
#define CPT    16       // candidates per thread
#define BUFSZ  192
#define GRID   888      // 6 blocks/SM on 148 SMs -> all co-resident
#define FULLM  0xffffffffu

// ---------------- device scratch ----------------
__device__ float2 g_vd[HEADS][HDIM];
__device__ float2 g_vs[HEADS][HDIM];
__device__ float4 g_sd[NN];
__device__ float4 g_ss[NN];
__device__ float  g_badj[NN];            // act_j ? 0.15*sum(ss_j) : -inf
__device__ int    g_cur[NN];
__device__ ulonglong2 g_edge[NN * CAP];  // .x = (pos<<32)|float_bits(w), .y = col
__device__ int    g_is_byte;
__device__ unsigned g_tick;
__device__ unsigned g_exit;

// ---------------- dynamic smem (~36.8 KB) ----------------
struct CSmem {
    float    corr[NN];               // 16 KB resolved corr weights (0 = none)
    unsigned kk[NN];                 // 16 KB staged keys
    unsigned long long buf[BUFSZ];   // 1.5 KB
    unsigned long long sel[TOPK];
    float    ewt[ECAP];
    int      ecol[ECAP];
    int      epos[ECAP];
    int      hist1[256];             // 1 KB, bins = key >> 24
    int      hist2[256];             // 1 KB, bins = (key >> 16) & 0xFF
    int      cnt, B1, above1, B2, above2, sbyte;
};

// ---------------- double-single helper ----------------
__device__ __forceinline__ void dsadd(float& s, float& c, float p, float pe) {
    float t = s + p;
    float z = t - s;
    float e = (s - (t - z)) + (p - z);
    s = t;
    c += e + pe;
}

// global barrier #gen (1-based)
__device__ __forceinline__ void gbar(int gen) {
    __syncthreads();
    if (threadIdx.x == 0) {
        __threadfence();
        atomicAdd(&g_tick, 1u);
        unsigned target = (unsigned)gen * GRID;
        while (*(volatile unsigned*)&g_tick < target) { }
    }
    __syncthreads();
}

// warp0: largest bin B (256 bins) with suffix-count >= K  (R7-proven)
__device__ __forceinline__ void scan_hist(const int* __restrict__ hist, int K,
                                          int* outB, int* outAbove) {
    int lane = threadIdx.x & 31;
    int base = lane * 8;
    int h[8];
    #pragma unroll
    for (int r = 0; r < 8; r++) h[r] = hist[base + r];
    int ls[8];
    int s = 0;
    #pragma unroll
    for (int r = 7; r >= 0; r--) { s += h[r]; ls[r] = s; }
    int run = s;
    #pragma unroll
    for (int off = 1; off < 32; off <<= 1) {
        int t = __shfl_down_sync(FULLM, run, off);
        if (lane + off < 32) run += t;
    }
    int above = run - s;
    int cand = -1, candAbove = 0;
    #pragma unroll
    for (int r = 7; r >= 0; r--) {
        if (cand < 0 && above + ls[r] >= K) {
            cand = base + r;
            candAbove = above + ls[r] - h[r];
        }
    }
    int bestB = cand, bestA = candAbove;
    #pragma unroll
    for (int off = 16; off; off >>= 1) {
        int ob = __shfl_xor_sync(FULLM, bestB, off);
        int oa = __shfl_xor_sync(FULLM, bestA, off);
        if (ob > bestB) { bestB = ob; bestA = oa; }
    }
    if (lane == 0) {
        *outB = (bestB < 0) ? 0 : bestB;
        *outAbove = (bestB < 0) ? 0 : bestA;
    }
}

// ---------------- the one fused kernel ----------------
__global__ __launch_bounds__(RT, 6) void k_all(const float* __restrict__ E,
                                               const float* __restrict__ W,
                                               const float* __restrict__ att,
                                               const float* __restrict__ lambda_p,
                                               const uint8_t* __restrict__ mask,
                                               const uint8_t* __restrict__ act,
                                               const int* __restrict__ eidx,
                                               const float* __restrict__ ew,
                                               float* __restrict__ out) {
    extern __shared__ CSmem smem[];
    CSmem* S = smem;

    const int bid = blockIdx.x;
    const int tid = threadIdx.x;
    const int lane = tid & 31;
    const int wid = tid >> 5;

    // ================= PHASE A =================
    if (bid < 16) {
        g_cur[bid * RT + tid] = 0;
    } else if (bid < 20) {
        int pr = (bid - 16) * RT + tid;   // 0..1023
        int h = pr >> 8;
        int k = pr & 255;
        float sd = 0.f, cd = 0.f, ss = 0.f, cs = 0.f;
        #pragma unroll 8
        for (int dd = 0; dd < HD; dd++) {
            float w   = W[(h * HD + dd) * HDIM + k];
            float ad  = att[h * 2 * HD + dd];
            float as_ = att[h * 2 * HD + HD + dd];
            float p = ad * w;  float pe = fmaf(ad, w, -p);
            dsadd(sd, cd, p, pe);
            p = as_ * w;       pe = fmaf(as_, w, -p);
            dsadd(ss, cs, p, pe);
        }
        float hi = sd + cd;
        g_vd[h][k] = make_float2(hi, (sd - hi) + cd);
        hi = ss + cs;
        g_vs[h][k] = make_float2(hi, (ss - hi) + cs);
    } else if (bid == 20) {
        if (tid == 0) S->sbyte = 0;
        __syncthreads();
        const unsigned* mw = (const unsigned*)mask;
        for (int t = tid; t < 4096; t += RT) {
            unsigned w = mw[t];
            if (w > 1u) {
                unsigned b0 = w & 0xFF, b1 = (w >> 8) & 0xFF,
                         b2 = (w >> 16) & 0xFF, b3 = w >> 24;
                if (b0 <= 1u && b1 <= 1u && b2 <= 1u && b3 <= 1u) S->sbyte = 1;
            }
        }
        __syncthreads();
        if (tid == 0) g_is_byte = S->sbyte;
    }
    gbar(1);

    // ================= PHASE B: sds (0..511) + scatter (512..887) ==========
    if (bid < 512) {
        int g = bid * 8 + wid;
        const float* er = E + (size_t)g * HDIM;
        float s[8], c[8];
        #pragma unroll
        for (int a = 0; a < 8; a++) { s[a] = 0.f; c[a] = 0.f; }
        for (int k = lane; k < HDIM; k += 32) {
            float e = er[k];
            #pragma unroll
            for (int h = 0; h < HEADS; h++) {
                float2 v = g_vd[h][k];
                float p = e * v.x;
                float pe = fmaf(e, v.x, -p);
                pe = fmaf(e, v.y, pe);
                dsadd(s[h], c[h], p, pe);
                v = g_vs[h][k];
                p = e * v.x;
                pe = fmaf(e, v.x, -p);
                pe = fmaf(e, v.y, pe);
                dsadd(s[4 + h], c[4 + h], p, pe);
            }
        }
        #pragma unroll
        for (int off = 16; off; off >>= 1) {
            #pragma unroll
            for (int a = 0; a < 8; a++) {
                float os = __shfl_down_sync(FULLM, s[a], off);
                float oc = __shfl_down_sync(FULLM, c[a], off);
                float t = s[a] + os;
                float z = t - s[a];
                c[a] += oc + ((s[a] - (t - z)) + (os - z));
                s[a] = t;
            }
        }
        if (lane == 0) {
            g_sd[g] = make_float4(s[0] + c[0], s[1] + c[1], s[2] + c[2], s[3] + c[3]);
            float t0 = s[4] + c[4], t1 = s[5] + c[5], t2 = s[6] + c[6], t3 = s[7] + c[7];
            g_ss[g] = make_float4(t0, t1, t2, t3);
            bool aj = g_is_byte ? (act[g] != 0) : (((const unsigned*)act)[g] != 0u);
            g_badj[g] = aj ? 0.15f * ((t0 + t1) + (t2 + t3)) : -INFINITY;
        }
    } else {
        for (int e = (bid - 512) * RT + tid; e < EC; e += 376 * RT) {
            int r = eidx[e];
            int cc = eidx[EC + e];
            int p = atomicAdd(&g_cur[r], 1);
            if (p < CAP) {
                ulonglong2 rec;
                rec.x = ((unsigned long long)(unsigned)e << 32) |
                        (unsigned long long)__float_as_uint(ew[e]);
                rec.y = (unsigned long long)(unsigned)cc;
                g_edge[r * CAP + p] = rec;
            }
        }
    }
    // zero this block's corr table once (maintained incrementally afterward)
    #pragma unroll
    for (int k = 0; k < NN / RT; k++) S->corr[tid + k * RT] = 0.f;
    gbar(2);

    // ================= PHASE C: rows =================
    const float lam = __ldg(lambda_p);
    const int is_byte = g_is_byte;

    for (int i = bid; i < NN; i += GRID) {
        // ---- P1: init + edge load + last-write-wins resolve ----
        S->hist1[tid] = 0;
        S->hist2[tid] = 0;
        if (tid < TOPK) S->sel[tid] = 0ULL;
        if (tid == RT - 1) S->cnt = 0;
        int cnt = g_cur[i];
        if (cnt > ECAP) cnt = ECAP;
        if (tid < cnt) {
            ulonglong2 rec = __ldg(&g_edge[i * CAP + tid]);
            S->ecol[tid] = (int)rec.y;
            S->epos[tid] = (int)(rec.x >> 32);
            S->ewt[tid]  = __uint_as_float((unsigned)rec.x);
        }
        __syncthreads();
        if (tid < cnt) {
            int c = S->ecol[tid], p = S->epos[tid];
            bool win = true;
            for (int s = 0; s < cnt; s++)
                if (S->ecol[s] == c && S->epos[s] > p) win = false;
            if (win) S->corr[c] = S->ewt[tid];
        }
        __syncthreads();

        const float4 sdi = __ldg(&g_sd[i]);
        const float ci = 0.15f * ((sdi.x + sdi.y) + (sdi.z + sdi.w));
        const uint8_t*  mrow8  = mask + (size_t)i * NN;
        const unsigned* mrow32 = (const unsigned*)mask + (size_t)i * NN;
        const bool acti = is_byte ? (act[i] != 0) : (((const unsigned*)act)[i] != 0u);

        // ---- P2: compute 16 keys -> smem + level-1 histogram ----
        #pragma unroll 8
        for (int k = 0; k < CPT; k++) {
            int j = tid + k * RT;
            float4 ssj = __ldg(&g_ss[j]);
            float x0 = sdi.x + ssj.x;
            float x1 = sdi.y + ssj.y;
            float x2 = sdi.z + ssj.z;
            float x3 = sdi.w + ssj.w;
            float sa = fabsf(x0) + fabsf(x1);
            float sb = fabsf(x2) + fabsf(x3);
            float w = S->corr[j];
            float a = __ldg(&g_badj[j]);
            bool mj = is_byte ? (mrow8[j] != 0) : (mrow32[j] != 0u);
            float sc = ci + fmaf(lam, w, a);
            sc = fmaf(0.1f, sa + sb, sc);
            sc = (acti && mj) ? sc : -INFINITY;
            unsigned u = __float_as_uint(sc);
            u ^= ((unsigned)(((int)u) >> 31)) | 0x80000000u;
            S->kk[j] = u;
            unsigned b1 = u >> 24;
            unsigned peers = __match_any_sync(FULLM, b1);
            if ((peers & ((1u << lane) - 1u)) == 0)
                atomicAdd(&S->hist1[b1], (int)__popc(peers));
        }
        __syncthreads();

        // ---- P3: warp0 scans level-1; other threads clear touched corr ----
        if (wid == 0) {
            scan_hist(S->hist1, TOPK, &S->B1, &S->above1);
        } else if (tid - 32 < cnt) {
            S->corr[S->ecol[tid - 32]] = 0.f;
        }
        __syncthreads();
        const int B1 = S->B1;
        const int above1 = S->above1;

        // ---- P4: level-2 histogram within bin B1 ----
        #pragma unroll 8
        for (int k = 0; k < CPT; k++) {
            unsigned u = S->kk[tid + k * RT];
            if ((int)(u >> 24) == B1)
                atomicAdd(&S->hist2[(u >> 16) & 0xFF], 1);
        }
        __syncthreads();

        // ---- P5: level-2 scan ----
        if (wid == 0) scan_hist(S->hist2, TOPK - above1, &S->B2, &S->above2);
        __syncthreads();
        const int B2 = S->B2;

        // ---- P6: append candidates ----
        #pragma unroll 8
        for (int k = 0; k < CPT; k++) {
            int j = tid + k * RT;
            unsigned u = S->kk[j];
            int b1k = (int)(u >> 24);
            bool cand = (b1k > B1) || (b1k == B1 && (int)((u >> 16) & 0xFF) >= B2);
            if (cand) {
                int p = atomicAdd(&S->cnt, 1);
                if (p < BUFSZ) {
                    S->buf[p] = ((unsigned long long)u << 32) |
                                (unsigned long long)(0xFFFFFFFFu - (unsigned)j);
                }
            }
        }
        __syncthreads();

        // ---- P7: rank-select top-15 ----
        int n = S->cnt < BUFSZ ? S->cnt : BUFSZ;
        {
            unsigned long long K = (tid < n) ? S->buf[tid] : 0ULL;
            int rank = 0;
            for (int s = 0; s < n; s++) rank += (S->buf[s] > K);
            if (tid < n && rank < TOPK) S->sel[rank] = K;
        }
        __syncthreads();

        // ---- P8: warp0 decode + softmax + write ----
        if (wid == 0) {
            unsigned long long k64 = (lane < TOPK) ? S->sel[lane] : 0ULL;
            unsigned u = (unsigned)(k64 >> 32);
            float v = (u & 0x80000000u) ? __uint_as_float(u ^ 0x80000000u)
                                        : __uint_as_float(~u);
            unsigned j = 0xFFFFFFFFu - (unsigned)(k64 & 0xFFFFFFFFu);
            float v0 = __shfl_sync(FULLM, v, 0);
            float e = (lane < TOPK) ? expf(v - v0) : 0.f;
            float s = e;
            #pragma unroll
            for (int off = 16; off; off >>= 1) s += __shfl_xor_sync(FULLM, s, off);
            if (lane < TOPK) {
                out[(size_t)i * TOPK + lane] = (float)j;
                out[(size_t)NN * TOPK + (size_t)i * TOPK + lane] = (float)i;
                out[2 * (size_t)NN * TOPK + (size_t)i * TOPK + lane] = e / s;
            }
        }
        __syncthreads();
    }

    // ================= epilogue: reset barrier counters =================
    if (tid == 0) {
        __threadfence();
        unsigned t = atomicAdd(&g_exit, 1u);
        if (t == GRID - 1) {
            g_tick = 0;
            g_exit = 0;
            __threadfence();
        }
    }
}

// ---------------- launcher ----------------
extern "C" void kernel_launch(void* const* d_in, const int* in_sizes, int n_in,
                              void* d_out, int out_size) {
    const float*   emb  = (const float*)d_in[0];
    const float*   W    = (const float*)d_in[1];
    const float*   att  = (const float*)d_in[2];
    const float*   lam  = (const float*)d_in[3];
    const uint8_t* mask = (const uint8_t*)d_in[4];
    const uint8_t* act  = (const uint8_t*)d_in[5];
    const int*     eidx = (const int*)d_in[6];
    const float*   ew   = (const float*)d_in[7];
    float* out = (float*)d_out;

    cudaFuncSetAttribute(k_all, cudaFuncAttributeMaxDynamicSharedMemorySize,
                         (int)sizeof(CSmem));
    k_all<<<GRID, RT, sizeof(CSmem)>>>(emb, W, att, lam, mask, act, eidx, ew, out);
}